// round 9
// baseline (speedup 1.0000x reference)
#include <cuda_runtime.h>
#include <cuda_fp16.h>
#include <math.h>
#include <stdint.h>

#define N_RAYS   4096
#define PSTEPS   254
#define P_INNER  231
#define MTOT     (N_RAYS*PSTEPS)      // 1,040,384
#define NT64     (MTOT/64)            // 16256
#define WORLD    160
#define S2       (WORLD*WORLD)
#define S3       (WORLD*WORLD*WORLD)
#define ACT_SHIFT (-9.210240371976183f)
#define BG_LEN   0.2f
#define GRID_MLP 296                  // 2 CTAs per SM

// ---------------- scratch ----------------
__device__ uint4    g_pack[S3*2];       // per-voxel record: 12 fp16 k0 + fp32 density + pad (32 B)
__device__ uint16_t g_f16[MTOT*16];     // k0 features fp16 rows (12 real + 4 pad)
__device__ float    g_vembf[N_RAYS*27]; // view embedding fp32
__device__ float    g_h0v[N_RAYS*128];  // per-ray layer0 contribution of vemb + b0
__device__ float    g_alpha[MTOT];
__device__ float    g_w[MTOT];

// ---------------- helpers ----------------
__device__ __forceinline__ uint16_t f2h(float f) {
    return __half_as_ushort(__float2half_rn(f));
}
__device__ __forceinline__ uint32_t pack_h2(float f0, float f1) {   // f0 -> low half
    __half2 v = __floats2half2_rn(f0, f1);
    return *reinterpret_cast<uint32_t*>(&v);
}
__device__ __forceinline__ uint32_t smem_u32(const void* p) {
    uint32_t a;
    asm("{ .reg .u64 t; cvta.to.shared.u64 t, %1; cvt.u32.u64 %0, t; }" : "=r"(a) : "l"(p));
    return a;
}

#define LDSM_X4(r0,r1,r2,r3,addr) \
    asm volatile("ldmatrix.sync.aligned.m8n8.x4.shared.b16 {%0,%1,%2,%3}, [%4];" \
        : "=r"(r0), "=r"(r1), "=r"(r2), "=r"(r3) : "r"(addr))

#define LDSM_X2(r0,r1,addr) \
    asm volatile("ldmatrix.sync.aligned.m8n8.x2.shared.b16 {%0,%1}, [%2];" \
        : "=r"(r0), "=r"(r1) : "r"(addr))

#define MMA_F16(c, a0,a1,a2,a3, b0,b1) \
    asm volatile("mma.sync.aligned.m16n8k16.row.col.f32.f16.f16.f32 " \
        "{%0,%1,%2,%3}, {%4,%5,%6,%7}, {%8,%9}, {%0,%1,%2,%3};" \
        : "+f"((c)[0]), "+f"((c)[1]), "+f"((c)[2]), "+f"((c)[3]) \
        : "r"(a0), "r"(a1), "r"(a2), "r"(a3), "r"(b0), "r"(b1))

// ---------------- K0: grid repack (channel-interleaved 32B records) ----------------
__global__ void k_pack(const float* __restrict__ dgrid, const float* __restrict__ k0g)
{
    int idx = blockIdx.x * blockDim.x + threadIdx.x;
    if (idx >= S3) return;
    uint32_t h[6];
    #pragma unroll
    for (int c = 0; c < 6; c++)
        h[c] = pack_h2(__ldg(&k0g[(2*c)*S3 + idx]), __ldg(&k0g[(2*c+1)*S3 + idx]));
    float d = __ldg(&dgrid[idx]);
    g_pack[(size_t)idx*2+0] = make_uint4(h[0], h[1], h[2], h[3]);
    g_pack[(size_t)idx*2+1] = make_uint4(h[4], h[5], __float_as_uint(d), 0u);
}

// ---------------- K1: sampling + contraction + trilinear interp (packed reads) ----------------
__global__ void k_sample(const float* __restrict__ ro, const float* __restrict__ rdir,
                         const int* __restrict__ stepsize)
{
    int s = blockIdx.x * blockDim.x + threadIdx.x;
    if (s >= MTOT) return;
    int r = s / PSTEPS;
    int p = s - r * PSTEPS;

    const float SQ3x2 = 3.4641016151377546f;
    float t;
    if (p < P_INNER) {
        t = SQ3x2 * ((float)p + 0.5f) * (1.0f / 231.0f);
    } else {
        int q = p - P_INNER;
        float L0 = 1.0f - (float)q     * (0.999f / 23.0f);
        float L1 = 1.0f - (float)(q+1) * (0.999f / 23.0f);
        t = 0.5f * SQ3x2 * (1.0f / L0 + 1.0f / L1);
    }

    float dx = rdir[r*3+0], dy = rdir[r*3+1], dz = rdir[r*3+2];
    float inv = rsqrtf(dx*dx + dy*dy + dz*dz);
    dx *= inv; dy *= inv; dz *= inv;

    float px = ro[r*3+0] + dx * t;
    float py = ro[r*3+1] + dy * t;
    float pz = ro[r*3+2] + dz * t;

    float nm = fmaxf(fabsf(px), fmaxf(fabsf(py), fabsf(pz)));
    if (nm > 1.0f) {
        float sc = (1.0f + BG_LEN - BG_LEN / nm) / nm;
        px *= sc; py *= sc; pz *= sc;
    }

    const float GS = 159.0f / 2.4f;
    float gx = fminf(fmaxf((px + 1.2f) * GS, 0.0f), 159.0f);
    float gy = fminf(fmaxf((py + 1.2f) * GS, 0.0f), 159.0f);
    float gz = fminf(fmaxf((pz + 1.2f) * GS, 0.0f), 159.0f);
    int ix = min((int)gx, 158);
    int iy = min((int)gy, 158);
    int iz = min((int)gz, 158);
    float fx = gx - (float)ix, fy = gy - (float)iy, fz = gz - (float)iz;

    int base = (ix * WORLD + iy) * WORLD + iz;
    float w00 = (1.f-fx)*(1.f-fy), w01 = (1.f-fx)*fy, w10 = fx*(1.f-fy), w11 = fx*fy;
    float wz0 = 1.f - fz, wz1 = fz;

    float wt[8];
    wt[0]=w00*wz0; wt[1]=w00*wz1; wt[2]=w01*wz0; wt[3]=w01*wz1;
    wt[4]=w10*wz0; wt[5]=w10*wz1; wt[6]=w11*wz0; wt[7]=w11*wz1;
    int off[8];
    off[0]=base;          off[1]=base+1;
    off[2]=base+WORLD;    off[3]=base+WORLD+1;
    off[4]=base+S2;       off[5]=base+S2+1;
    off[6]=base+S2+WORLD; off[7]=base+S2+WORLD+1;

    float acc[12];
    #pragma unroll
    for (int c = 0; c < 12; c++) acc[c] = 0.0f;
    float dsum = 0.0f;

    #pragma unroll
    for (int u = 0; u < 8; u++) {
        const uint4* rec = &g_pack[(size_t)off[u]*2];
        uint4 qa = __ldg(&rec[0]);
        uint4 qb = __ldg(&rec[1]);
        float wtu = wt[u];
        float2 f;
        f = __half22float2(*(const __half2*)&qa.x); acc[0] += wtu*f.x; acc[1] += wtu*f.y;
        f = __half22float2(*(const __half2*)&qa.y); acc[2] += wtu*f.x; acc[3] += wtu*f.y;
        f = __half22float2(*(const __half2*)&qa.z); acc[4] += wtu*f.x; acc[5] += wtu*f.y;
        f = __half22float2(*(const __half2*)&qa.w); acc[6] += wtu*f.x; acc[7] += wtu*f.y;
        f = __half22float2(*(const __half2*)&qb.x); acc[8] += wtu*f.x; acc[9] += wtu*f.y;
        f = __half22float2(*(const __half2*)&qb.y); acc[10]+= wtu*f.x; acc[11]+= wtu*f.y;
        dsum += wtu * __uint_as_float(qb.z);
    }

    int sv = *stepsize;
    float interval = (sv > 0 && sv < 1000000) ? (float)sv : __int_as_float(sv);

    float x = dsum + ACT_SHIFT;
    float sp = (x > 20.0f) ? x : log1pf(expf(x));
    g_alpha[s] = 1.0f - expf(-interval * sp);

    uint32_t ph[8];
    #pragma unroll
    for (int c = 0; c < 6; c++) ph[c] = pack_h2(acc[2*c], acc[2*c+1]);
    ph[6] = ph[7] = 0u;
    uint4* dh = (uint4*)&g_f16[(size_t)s*16];
    dh[0] = make_uint4(ph[0],ph[1],ph[2],ph[3]);
    dh[1] = make_uint4(ph[4],ph[5],ph[6],ph[7]);
}

// ---------------- K2: warp-parallel view embedding + transmittance scan ----------------
__global__ void k_scan(const float* __restrict__ vdirs, float* __restrict__ out)
{
    int gw = (blockIdx.x * blockDim.x + threadIdx.x) >> 5;   // ray id
    int lane = threadIdx.x & 31;
    if (gw >= N_RAYS) return;

    float d0 = __ldg(&vdirs[gw*3+0]);
    float d1 = __ldg(&vdirs[gw*3+1]);
    float d2 = __ldg(&vdirs[gw*3+2]);

    if (lane < 27) {
        float v;
        if (lane < 3) {
            v = (lane == 0) ? d0 : (lane == 1) ? d1 : d2;
        } else {
            int kk = (lane < 15) ? (lane - 3) : (lane - 15);
            int c = kk >> 2, e = kk & 3;
            float dc = (c == 0) ? d0 : (c == 1) ? d1 : d2;
            float vv = dc * (float)(1 << e);
            v = (lane < 15) ? sinf(vv) : cosf(vv);
        }
        g_vembf[gw*27 + lane] = v;
    }

    float T = 1.0f;
    int base = gw * PSTEPS;
    #pragma unroll
    for (int chunk = 0; chunk < 8; chunk++) {
        int p = chunk*32 + lane;
        float a = (p < PSTEPS) ? g_alpha[base + p] : 0.0f;
        float q = 1.0f - a;
        float incl = q;
        #pragma unroll
        for (int dlt = 1; dlt < 32; dlt <<= 1) {
            float o = __shfl_up_sync(0xffffffffu, incl, dlt);
            if (lane >= dlt) incl *= o;
        }
        float excl = __shfl_up_sync(0xffffffffu, incl, 1);
        if (lane == 0) excl = 1.0f;
        if (p < PSTEPS) g_w[base + p] = a * T * excl;
        float tot = __shfl_sync(0xffffffffu, incl, 31);
        T *= tot;
    }
    if (lane == 0) {
        out[gw*3+0] = T; out[gw*3+1] = T; out[gw*3+2] = T;   // BG = 1.0
    }
}

// ---------------- K2b: per-ray layer0 view contribution: h0v = b0 + vemb @ W0[12:39] ----------------
__global__ void k_h0v(const float* __restrict__ w0, const float* __restrict__ b0)
{
    int gid = blockIdx.x * blockDim.x + threadIdx.x;
    int r = gid >> 7, n = gid & 127;
    float acc = __ldg(&b0[n]);
    #pragma unroll
    for (int k = 0; k < 27; k++)
        acc = fmaf(g_vembf[r*27 + k], __ldg(&w0[(12+k)*128 + n]), acc);
    g_h0v[r*128 + n] = acc;
}

// ---------------- K3: persistent fp16 MLP, 64-row tiles, 8 warps (4 rgrp x 2 half), 2 CTAs/SM ----------------
// smem layout (bytes)
#define SM_B1V   0        // 512:   b1 (128 f)
#define SM_PR    512      // 2048:  [4 rgrp][2 half][16 slot][4 f]
#define SM_H0    2560     // 2048:  [2 buf][2 rays][128 f]
#define SM_A0    4608     // 6144:  [2 buf][64 rows][48 B]
#define SM_B0    10752    // 6144:  [128 n][48 B]
#define SM_B1    16896    // 34816: [128 n][272 B]
#define SM_B2    51712    // 2176:  [8 n][272 B]
#define SM_A1    53888    // 17408: [64 rows][272 B]
#define SMEM_TOTAL 71296

__global__ void __launch_bounds__(256, 2) k_mlp(
    const float* __restrict__ w0, const float* __restrict__ b0,
    const float* __restrict__ w1, const float* __restrict__ b1,
    const float* __restrict__ w2, const float* __restrict__ b2,
    float* __restrict__ out)
{
    extern __shared__ unsigned char smem[];
    uint32_t sb = smem_u32(smem);
    int tid = threadIdx.x;
    int w = tid >> 5, l = tid & 31;
    int g = l >> 2, tg = l & 3;
    int rgrp = w & 3, half = w >> 2;

    // ---- one-time weight staging (fp16, [n][k] layout) ----
    if (tid < 128) ((float*)(smem + SM_B1V))[tid] = b1[tid];
    for (int idx = tid; idx < 128*16; idx += 256) {
        int n = idx & 127, k = idx >> 7;
        float v = (k < 12) ? w0[k*128 + n] : 0.0f;
        *(uint16_t*)(smem + SM_B0 + n*48 + k*2) = f2h(v);
    }
    for (int idx = tid; idx < 128*128; idx += 256) {
        int n = idx & 127, k = idx >> 7;
        *(uint16_t*)(smem + SM_B1 + n*272 + k*2) = f2h(w1[k*128 + n]);
    }
    for (int idx = tid; idx < 8*128; idx += 256) {
        int n = idx & 7, k = idx >> 3;
        float v = (n < 3) ? w2[k*3 + n] : 0.0f;
        *(uint16_t*)(smem + SM_B2 + n*272 + k*2) = f2h(v);
    }
    float b2r0 = __ldg(&b2[0]), b2r1 = __ldg(&b2[1]), b2r2 = __ldg(&b2[2]);
    const float* b1s = (const float*)(smem + SM_B1V);

    // ---- lane-invariant ldmatrix addresses ----
    uint32_t rowl = (uint32_t)((l & 7) + ((l >> 3) & 1) * 8);   // 0..15 within row-group
    uint32_t colq = (uint32_t)(l >> 4) * 16;
    uint32_t aA0base = sb + SM_A0 + (rgrp*16 + rowl)*48 + colq;
    uint32_t aA1 = sb + SM_A1 + (rgrp*16 + rowl)*272 + colq;
    uint32_t lrow = (uint32_t)((l & 7) + ((l >> 4) & 1) * 8);
    uint32_t lcol = (uint32_t)(((l >> 3) & 1) * 16);
    uint32_t aB0 = sb + SM_B0 + lrow*48  + lcol;
    uint32_t aB1 = sb + SM_B1 + lrow*272 + lcol;
    uint32_t aB2 = sb + SM_B2 + (uint32_t)(l & 7)*272 + (uint32_t)(((l >> 3) & 1) * 16);

    // ---- prime buffer 0 ----
    int m = blockIdx.x;
    if (m < NT64) {
        if (tid < 128) {
            int row = tid >> 1, part = tid & 1;
            uint4 q = *(const uint4*)&g_f16[(size_t)(m*64 + row)*16 + part*8];
            *(uint4*)(smem + SM_A0 + row*48 + part*16) = q;
        }
        int rA = (m*64) / PSTEPS, rB = (m*64 + 63) / PSTEPS;
        float* hs = (float*)(smem + SM_H0);
        hs[tid] = (tid < 128) ? g_h0v[(size_t)rA*128 + tid]
                              : g_h0v[(size_t)rB*128 + (tid - 128)];
    }
    __syncthreads();

    // ---- preload layer-2 B fragments (tile-invariant) ----
    uint32_t b2f[8][2];
    #pragma unroll
    for (int ks = 0; ks < 8; ks++) LDSM_X2(b2f[ks][0], b2f[ks][1], aB2 + ks*32);

    int buf = 0;

    for (; m < NT64; m += gridDim.x) {
        int mbase = m * 64;
        int mn = m + gridDim.x;
        bool hn = mn < NT64;
        uint4 qn;
        float hn_val = 0.f;
        if (hn) {
            if (tid < 128) {
                int row = tid >> 1, part = tid & 1;
                qn = *(const uint4*)&g_f16[(size_t)(mn*64 + row)*16 + part*8];
            }
            int rAn = (mn*64) / PSTEPS, rBn = (mn*64 + 63) / PSTEPS;
            hn_val = (tid < 128) ? g_h0v[(size_t)rAn*128 + tid]
                                 : g_h0v[(size_t)rBn*128 + (tid - 128)];
        }

        int rayA = mbase / PSTEPS;
        int bnd  = (rayA + 1) * PSTEPS;
        int sg   = mbase + rgrp*16 + g;
        int sg8  = sg + 8;
        const float* hs   = (const float*)(smem + SM_H0 + (uint32_t)buf*1024u);
        const float* hpg  = hs + ((sg  >= bnd) ? 128 : 0);
        const float* hpg8 = hs + ((sg8 >= bnd) ? 128 : 0);

        // ---- layer 0: K=16, this warp's 4 n-chunks -> relu'd h1 into A1 smem ----
        uint32_t aA0 = aA0base + (uint32_t)buf*3072u;
        uint32_t a00,a01,a02,a03;
        LDSM_X4(a00,a01,a02,a03, aA0);

        #pragma unroll
        for (int pc = 0; pc < 4; pc++) {
            int p = half*4 + pc;
            float cc0[4] = {0.f,0.f,0.f,0.f}, cc1[4] = {0.f,0.f,0.f,0.f};
            uint32_t bb0,bb1,bb2,bb3;
            LDSM_X4(bb0,bb1,bb2,bb3, aB0 + p*768);
            MMA_F16(cc0, a00,a01,a02,a03, bb0,bb1);
            MMA_F16(cc1, a00,a01,a02,a03, bb2,bb3);
            #pragma unroll
            for (int hh = 0; hh < 2; hh++) {
                const float* c4 = hh ? cc1 : cc0;
                int col = p*16 + hh*8 + tg*2;
                float2 hA = *(const float2*)&hpg[col];
                float2 hB = *(const float2*)&hpg8[col];
                uint32_t v0 = pack_h2(fmaxf(c4[0] + hA.x, 0.f), fmaxf(c4[1] + hA.y, 0.f));
                uint32_t v1 = pack_h2(fmaxf(c4[2] + hB.x, 0.f), fmaxf(c4[3] + hB.y, 0.f));
                *(uint32_t*)(smem + SM_A1 + (rgrp*16 + g)*272     + col*2) = v0;
                *(uint32_t*)(smem + SM_A1 + (rgrp*16 + g + 8)*272 + col*2) = v1;
            }
        }
        __syncthreads();   // A1 complete (both halves)

        // ---- layer 1 (this warp's 4 n-chunks) + layer 2 partial MMA ----
        uint32_t aF[8][4];
        #pragma unroll
        for (int ks = 0; ks < 8; ks++)
            LDSM_X4(aF[ks][0],aF[ks][1],aF[ks][2],aF[ks][3], aA1 + ks*32);

        float c2[4] = {0.f,0.f,0.f,0.f};
        #pragma unroll
        for (int pc = 0; pc < 4; pc++) {
            int p = half*4 + pc;
            float cc0[4] = {0.f,0.f,0.f,0.f}, cc1[4] = {0.f,0.f,0.f,0.f};
            #pragma unroll
            for (int ks = 0; ks < 8; ks++) {
                uint32_t bb0,bb1,bb2,bb3;
                LDSM_X4(bb0,bb1,bb2,bb3, aB1 + p*4352 + ks*32);
                MMA_F16(cc0, aF[ks][0],aF[ks][1],aF[ks][2],aF[ks][3], bb0,bb1);
                MMA_F16(cc1, aF[ks][0],aF[ks][1],aF[ks][2],aF[ks][3], bb2,bb3);
            }
            uint32_t hf[4];
            #pragma unroll
            for (int hh = 0; hh < 2; hh++) {
                const float* c4 = hh ? cc1 : cc0;
                int col = p*16 + hh*8 + tg*2;
                float f0 = fmaxf(c4[0] + b1s[col],   0.f);
                float f1 = fmaxf(c4[1] + b1s[col+1], 0.f);
                float f2 = fmaxf(c4[2] + b1s[col],   0.f);
                float f3 = fmaxf(c4[3] + b1s[col+1], 0.f);
                hf[0+hh*2] = pack_h2(f0, f1);
                hf[1+hh*2] = pack_h2(f2, f3);
            }
            MMA_F16(c2, hf[0],hf[1],hf[2],hf[3], b2f[p][0], b2f[p][1]);
        }

        if (tg < 2) {
            float* pr = (float*)(smem + SM_PR) + ((size_t)((rgrp*2 + half)*16 + g*2 + tg))*4;
            pr[0] = c2[0]; pr[1] = c2[1]; pr[2] = c2[2]; pr[3] = c2[3];
        }

        // ---- stage next tile into alternate buffers ----
        if (hn) {
            if (tid < 128) {
                int row = tid >> 1, part = tid & 1;
                *(uint4*)(smem + SM_A0 + (uint32_t)(buf^1)*3072u + row*48 + part*16) = qn;
            }
            ((float*)(smem + SM_H0 + (uint32_t)(buf^1)*1024u))[tid] = hn_val;
        }
        __syncthreads();   // PR ready, A1 reads done, staging done

        // ---- combine partner halves + sigmoid + weighted atomic (half 0 only) ----
        if (half == 0 && tg < 2) {
            const float* pr = (const float*)(smem + SM_PR) + ((size_t)((rgrp*2 + 1)*16 + g*2 + tg))*4;
            float t0 = c2[0] + pr[0], t1 = c2[1] + pr[1];
            float t2 = c2[2] + pr[2], t3 = c2[3] + pr[3];
            int rg  = sg  / PSTEPS;
            int rg8 = sg8 / PSTEPS;
            float wg0 = g_w[sg], wg1 = g_w[sg8];
            if (tg == 0) {
                atomicAdd(&out[rg*3+0],  wg0 / (1.0f + __expf(-(t0 + b2r0))));
                atomicAdd(&out[rg*3+1],  wg0 / (1.0f + __expf(-(t1 + b2r1))));
                atomicAdd(&out[rg8*3+0], wg1 / (1.0f + __expf(-(t2 + b2r0))));
                atomicAdd(&out[rg8*3+1], wg1 / (1.0f + __expf(-(t3 + b2r1))));
            } else {
                atomicAdd(&out[rg*3+2],  wg0 / (1.0f + __expf(-(t0 + b2r2))));
                atomicAdd(&out[rg8*3+2], wg1 / (1.0f + __expf(-(t2 + b2r2))));
            }
        }
        buf ^= 1;
    }
}

// ---------------- launcher ----------------
extern "C" void kernel_launch(void* const* d_in, const int* in_sizes, int n_in,
                              void* d_out, int out_size)
{
    const float* rays_o   = (const float*)d_in[0];
    const float* rays_d   = (const float*)d_in[1];
    const float* viewdirs = (const float*)d_in[2];
    const float* dgrid    = (const float*)d_in[3];
    const float* k0g      = (const float*)d_in[4];
    const float* w0 = (const float*)d_in[5];
    const float* b0 = (const float*)d_in[6];
    const float* w1 = (const float*)d_in[7];
    const float* b1 = (const float*)d_in[8];
    const float* w2 = (const float*)d_in[9];
    const float* b2 = (const float*)d_in[10];
    const int* stepsize = (const int*)d_in[11];
    float* out = (float*)d_out;

    cudaFuncSetAttribute(k_mlp, cudaFuncAttributeMaxDynamicSharedMemorySize, SMEM_TOTAL);

    k_pack<<<(S3 + 255) / 256, 256>>>(dgrid, k0g);
    k_sample<<<(MTOT + 255) / 256, 256>>>(rays_o, rays_d, stepsize);
    k_scan<<<(N_RAYS * 32 + 255) / 256, 256>>>(viewdirs, out);
    k_h0v<<<(N_RAYS * 128) / 256, 256>>>(w0, b0);
    k_mlp<<<GRID_MLP, 256, SMEM_TOTAL>>>(w0, b0, w1, b1, w2, b2, out);
}

// round 10
// speedup vs baseline: 1.0870x; 1.0870x over previous
#include <cuda_runtime.h>
#include <cuda_fp16.h>
#include <math.h>
#include <stdint.h>

#define N_RAYS   4096
#define PSTEPS   254
#define P_INNER  231
#define MTOT     (N_RAYS*PSTEPS)      // 1,040,384
#define NTILES   (MTOT/128)           // 8128
#define WORLD    160
#define S2       (WORLD*WORLD)
#define S3       (WORLD*WORLD*WORLD)
#define ACT_SHIFT (-9.210240371976183f)
#define BG_LEN   0.2f
#define GRID_MLP 592                  // 4 CTAs per SM

// ---------------- scratch ----------------
__device__ uint4    g_pack[S3*2];       // per-voxel record: 12 fp16 k0 + fp32 density + pad (32 B)
__device__ uint16_t g_f16[MTOT*16];     // k0 features fp16 rows (12 real + 4 pad)
__device__ float    g_vembf[N_RAYS*27]; // view embedding fp32
__device__ uint16_t g_h0v[N_RAYS*128];  // per-ray layer0 contribution of vemb + b0 (fp16)
__device__ float    g_alpha[MTOT];
__device__ float    g_w[MTOT];

// ---------------- helpers ----------------
__device__ __forceinline__ uint16_t f2h(float f) {
    return __half_as_ushort(__float2half_rn(f));
}
__device__ __forceinline__ uint32_t pack_h2(float f0, float f1) {   // f0 -> low half
    __half2 v = __floats2half2_rn(f0, f1);
    return *reinterpret_cast<uint32_t*>(&v);
}
__device__ __forceinline__ uint32_t smem_u32(const void* p) {
    uint32_t a;
    asm("{ .reg .u64 t; cvta.to.shared.u64 t, %1; cvt.u32.u64 %0, t; }" : "=r"(a) : "l"(p));
    return a;
}

#define LDSM_X4(r0,r1,r2,r3,addr) \
    asm volatile("ldmatrix.sync.aligned.m8n8.x4.shared.b16 {%0,%1,%2,%3}, [%4];" \
        : "=r"(r0), "=r"(r1), "=r"(r2), "=r"(r3) : "r"(addr))

#define LDSM_X2(r0,r1,addr) \
    asm volatile("ldmatrix.sync.aligned.m8n8.x2.shared.b16 {%0,%1}, [%2];" \
        : "=r"(r0), "=r"(r1) : "r"(addr))

#define MMA_F16(c, a0,a1,a2,a3, b0,b1) \
    asm volatile("mma.sync.aligned.m16n8k16.row.col.f32.f16.f16.f32 " \
        "{%0,%1,%2,%3}, {%4,%5,%6,%7}, {%8,%9}, {%0,%1,%2,%3};" \
        : "+f"((c)[0]), "+f"((c)[1]), "+f"((c)[2]), "+f"((c)[3]) \
        : "r"(a0), "r"(a1), "r"(a2), "r"(a3), "r"(b0), "r"(b1))

#define CP_ASYNC16(dst, src) \
    asm volatile("cp.async.cg.shared.global [%0], [%1], 16;" :: "r"(dst), "l"(src) : "memory")
#define CP_ASYNC4(dst, src) \
    asm volatile("cp.async.ca.shared.global [%0], [%1], 4;" :: "r"(dst), "l"(src) : "memory")
#define CP_COMMIT() asm volatile("cp.async.commit_group;" ::: "memory")
#define CP_WAIT0()  asm volatile("cp.async.wait_group 0;" ::: "memory")

// ---------------- K0: grid repack (channel-interleaved 32B records) ----------------
__global__ void k_pack(const float* __restrict__ dgrid, const float* __restrict__ k0g)
{
    int idx = blockIdx.x * blockDim.x + threadIdx.x;
    if (idx >= S3) return;
    uint32_t h[6];
    #pragma unroll
    for (int c = 0; c < 6; c++)
        h[c] = pack_h2(__ldg(&k0g[(2*c)*S3 + idx]), __ldg(&k0g[(2*c+1)*S3 + idx]));
    float d = __ldg(&dgrid[idx]);
    g_pack[(size_t)idx*2+0] = make_uint4(h[0], h[1], h[2], h[3]);
    g_pack[(size_t)idx*2+1] = make_uint4(h[4], h[5], __float_as_uint(d), 0u);
}

// ---------------- K1: sampling + contraction + trilinear interp (packed reads) ----------------
__global__ void k_sample(const float* __restrict__ ro, const float* __restrict__ rdir,
                         const int* __restrict__ stepsize)
{
    int s = blockIdx.x * blockDim.x + threadIdx.x;
    if (s >= MTOT) return;
    int r = s / PSTEPS;
    int p = s - r * PSTEPS;

    const float SQ3x2 = 3.4641016151377546f;
    float t;
    if (p < P_INNER) {
        t = SQ3x2 * ((float)p + 0.5f) * (1.0f / 231.0f);
    } else {
        int q = p - P_INNER;
        float L0 = 1.0f - (float)q     * (0.999f / 23.0f);
        float L1 = 1.0f - (float)(q+1) * (0.999f / 23.0f);
        t = 0.5f * SQ3x2 * (1.0f / L0 + 1.0f / L1);
    }

    float dx = rdir[r*3+0], dy = rdir[r*3+1], dz = rdir[r*3+2];
    float inv = rsqrtf(dx*dx + dy*dy + dz*dz);
    dx *= inv; dy *= inv; dz *= inv;

    float px = ro[r*3+0] + dx * t;
    float py = ro[r*3+1] + dy * t;
    float pz = ro[r*3+2] + dz * t;

    float nm = fmaxf(fabsf(px), fmaxf(fabsf(py), fabsf(pz)));
    if (nm > 1.0f) {
        float sc = (1.0f + BG_LEN - BG_LEN / nm) / nm;
        px *= sc; py *= sc; pz *= sc;
    }

    const float GS = 159.0f / 2.4f;
    float gx = fminf(fmaxf((px + 1.2f) * GS, 0.0f), 159.0f);
    float gy = fminf(fmaxf((py + 1.2f) * GS, 0.0f), 159.0f);
    float gz = fminf(fmaxf((pz + 1.2f) * GS, 0.0f), 159.0f);
    int ix = min((int)gx, 158);
    int iy = min((int)gy, 158);
    int iz = min((int)gz, 158);
    float fx = gx - (float)ix, fy = gy - (float)iy, fz = gz - (float)iz;

    int base = (ix * WORLD + iy) * WORLD + iz;
    float w00 = (1.f-fx)*(1.f-fy), w01 = (1.f-fx)*fy, w10 = fx*(1.f-fy), w11 = fx*fy;
    float wz0 = 1.f - fz, wz1 = fz;

    float wt[8];
    wt[0]=w00*wz0; wt[1]=w00*wz1; wt[2]=w01*wz0; wt[3]=w01*wz1;
    wt[4]=w10*wz0; wt[5]=w10*wz1; wt[6]=w11*wz0; wt[7]=w11*wz1;
    int off[8];
    off[0]=base;          off[1]=base+1;
    off[2]=base+WORLD;    off[3]=base+WORLD+1;
    off[4]=base+S2;       off[5]=base+S2+1;
    off[6]=base+S2+WORLD; off[7]=base+S2+WORLD+1;

    float acc[12];
    #pragma unroll
    for (int c = 0; c < 12; c++) acc[c] = 0.0f;
    float dsum = 0.0f;

    #pragma unroll
    for (int u = 0; u < 8; u++) {
        const uint4* rec = &g_pack[(size_t)off[u]*2];
        uint4 qa = __ldg(&rec[0]);
        uint4 qb = __ldg(&rec[1]);
        float wtu = wt[u];
        float2 f;
        f = __half22float2(*(const __half2*)&qa.x); acc[0] += wtu*f.x; acc[1] += wtu*f.y;
        f = __half22float2(*(const __half2*)&qa.y); acc[2] += wtu*f.x; acc[3] += wtu*f.y;
        f = __half22float2(*(const __half2*)&qa.z); acc[4] += wtu*f.x; acc[5] += wtu*f.y;
        f = __half22float2(*(const __half2*)&qa.w); acc[6] += wtu*f.x; acc[7] += wtu*f.y;
        f = __half22float2(*(const __half2*)&qb.x); acc[8] += wtu*f.x; acc[9] += wtu*f.y;
        f = __half22float2(*(const __half2*)&qb.y); acc[10]+= wtu*f.x; acc[11]+= wtu*f.y;
        dsum += wtu * __uint_as_float(qb.z);
    }

    int sv = *stepsize;
    float interval = (sv > 0 && sv < 1000000) ? (float)sv : __int_as_float(sv);

    float x = dsum + ACT_SHIFT;
    float sp = (x > 20.0f) ? x : log1pf(expf(x));
    g_alpha[s] = 1.0f - expf(-interval * sp);

    uint32_t ph[8];
    #pragma unroll
    for (int c = 0; c < 6; c++) ph[c] = pack_h2(acc[2*c], acc[2*c+1]);
    ph[6] = ph[7] = 0u;
    uint4* dh = (uint4*)&g_f16[(size_t)s*16];
    dh[0] = make_uint4(ph[0],ph[1],ph[2],ph[3]);
    dh[1] = make_uint4(ph[4],ph[5],ph[6],ph[7]);
}

// ---------------- K2: warp-parallel view embedding + transmittance scan ----------------
__global__ void k_scan(const float* __restrict__ vdirs, float* __restrict__ out)
{
    int gw = (blockIdx.x * blockDim.x + threadIdx.x) >> 5;   // ray id
    int lane = threadIdx.x & 31;
    if (gw >= N_RAYS) return;

    float d0 = __ldg(&vdirs[gw*3+0]);
    float d1 = __ldg(&vdirs[gw*3+1]);
    float d2 = __ldg(&vdirs[gw*3+2]);

    if (lane < 27) {
        float v;
        if (lane < 3) {
            v = (lane == 0) ? d0 : (lane == 1) ? d1 : d2;
        } else {
            int kk = (lane < 15) ? (lane - 3) : (lane - 15);
            int c = kk >> 2, e = kk & 3;
            float dc = (c == 0) ? d0 : (c == 1) ? d1 : d2;
            float vv = dc * (float)(1 << e);
            v = (lane < 15) ? sinf(vv) : cosf(vv);
        }
        g_vembf[gw*27 + lane] = v;
    }

    float T = 1.0f;
    int base = gw * PSTEPS;
    #pragma unroll
    for (int chunk = 0; chunk < 8; chunk++) {
        int p = chunk*32 + lane;
        float a = (p < PSTEPS) ? g_alpha[base + p] : 0.0f;
        float q = 1.0f - a;
        float incl = q;
        #pragma unroll
        for (int dlt = 1; dlt < 32; dlt <<= 1) {
            float o = __shfl_up_sync(0xffffffffu, incl, dlt);
            if (lane >= dlt) incl *= o;
        }
        float excl = __shfl_up_sync(0xffffffffu, incl, 1);
        if (lane == 0) excl = 1.0f;
        if (p < PSTEPS) g_w[base + p] = a * T * excl;
        float tot = __shfl_sync(0xffffffffu, incl, 31);
        T *= tot;
    }
    if (lane == 0) {
        out[gw*3+0] = T; out[gw*3+1] = T; out[gw*3+2] = T;   // BG = 1.0
    }
}

// ---------------- K2b: per-ray layer0 view contribution (fp16): h0v = b0 + vemb @ W0[12:39] ----------------
__global__ void k_h0v(const float* __restrict__ w0, const float* __restrict__ b0)
{
    int gid = blockIdx.x * blockDim.x + threadIdx.x;
    int r = gid >> 7, n = gid & 127;
    float acc = __ldg(&b0[n]);
    #pragma unroll
    for (int k = 0; k < 27; k++)
        acc = fmaf(g_vembf[r*27 + k], __ldg(&w0[(12+k)*128 + n]), acc);
    g_h0v[r*128 + n] = f2h(acc);
}

// ---------------- K3: persistent fp16 mma.sync MLP (layer2 as MMA), 128 thr, 4 CTAs/SM ----------------
// smem layout (bytes)
#define SM_B1V   0        // 512:   b1 (128 f)
#define SM_H0    512      // 1024:  [2 buf][2 rays][128 half]
#define SM_A0    1536     // 12288: [2 buf][128 rows][48 B]
#define SM_B0    13824    // 6144:  [128 n][48 B] (k 0..15 real)
#define SM_B1    19968    // 34816: [128 n][272 B] (k 0..127 real)
#define SM_B2    54784    // 2176:  [8 n][272 B] (n 0..2 real)
#define SMEM_TOTAL 56960

__global__ void __launch_bounds__(128, 4) k_mlp(
    const float* __restrict__ w0, const float* __restrict__ b0,
    const float* __restrict__ w1, const float* __restrict__ b1,
    const float* __restrict__ w2, const float* __restrict__ b2,
    float* __restrict__ out)
{
    extern __shared__ unsigned char smem[];
    uint32_t sb = smem_u32(smem);
    int tid = threadIdx.x;
    int w = tid >> 5, l = tid & 31;
    int g = l >> 2, tg = l & 3;

    // ---- one-time weight staging (fp16, [n][k] layout) ----
    if (tid < 128) ((float*)(smem + SM_B1V))[tid] = b1[tid];

    for (int idx = tid; idx < 128*16; idx += 128) {
        int n = idx & 127, k = idx >> 7;
        float v = (k < 12) ? w0[k*128 + n] : 0.0f;
        *(uint16_t*)(smem + SM_B0 + n*48 + k*2) = f2h(v);
    }
    for (int idx = tid; idx < 128*128; idx += 128) {
        int n = idx & 127, k = idx >> 7;
        *(uint16_t*)(smem + SM_B1 + n*272 + k*2) = f2h(w1[k*128 + n]);
    }
    for (int idx = tid; idx < 8*128; idx += 128) {
        int n = idx & 7, k = idx >> 3;
        float v = (n < 3) ? w2[k*3 + n] : 0.0f;
        *(uint16_t*)(smem + SM_B2 + n*272 + k*2) = f2h(v);
    }
    float b2r0 = __ldg(&b2[0]), b2r1 = __ldg(&b2[1]), b2r2 = __ldg(&b2[2]);
    const float* b1s = (const float*)(smem + SM_B1V);

    // ---- lane-invariant ldmatrix addresses ----
    uint32_t rowA = 32u*w + (l & 7) + ((l >> 3) & 1) * 8;   // block 0; block 1 = +16 rows (768B)
    uint32_t colA = (uint32_t)(l >> 4) * 16;
    uint32_t lrow = (l & 7) + ((l >> 4) & 1) * 8;
    uint32_t lcol = ((l >> 3) & 1) * 16;
    uint32_t aB0 = sb + SM_B0 + lrow*48  + lcol;
    uint32_t aB1 = sb + SM_B1 + lrow*272 + lcol;
    uint32_t aB2 = sb + SM_B2 + (uint32_t)(l & 7)*272 + ((l >> 3) & 1)*16;

    int srow = tid;   // each thread stages one full row (32 B)

    // staging helper addresses
    uint32_t a0dst0 = sb + SM_A0 + srow*48;

    // ---- prime A0 + H0 buffer 0 (cp.async) ----
    int m = blockIdx.x;
    if (m < NTILES) {
        const char* src = (const char*)&g_f16[(size_t)(m*128+srow)*16];
        CP_ASYNC16(a0dst0,      src);
        CP_ASYNC16(a0dst0 + 16, src + 16);
        int rA = (m*128) / PSTEPS;
        int rB = (m*128 + 127) / PSTEPS;
        int ray = (tid < 64) ? rA : rB;
        int li  = (tid < 64) ? tid : (tid - 64);
        CP_ASYNC4(sb + SM_H0 + (uint32_t)(tid < 64 ? 0 : 256) + li*4,
                  (const char*)&g_h0v[(size_t)ray*128 + li*2]);
        CP_COMMIT();
        CP_WAIT0();
    }
    __syncthreads();

    // ---- preload layer-2 B fragments (tile-invariant) ----
    uint32_t b2f[8][2];
    #pragma unroll
    for (int p = 0; p < 8; p++) LDSM_X2(b2f[p][0], b2f[p][1], aB2 + p*32);

    int buf = 0;

    for (; m < NTILES; m += gridDim.x) {
        int mbase = m * 128;
        int mn = m + gridDim.x;
        bool hn = mn < NTILES;
        if (hn) {   // async-stage next tile into alternate buffer (hidden under compute)
            uint32_t ab = a0dst0 + (uint32_t)(buf^1)*6144u;
            const char* src = (const char*)&g_f16[(size_t)(mn*128+srow)*16];
            CP_ASYNC16(ab,      src);
            CP_ASYNC16(ab + 16, src + 16);
            int rAn = (mn*128) / PSTEPS;
            int rBn = (mn*128 + 127) / PSTEPS;
            int ray = (tid < 64) ? rAn : rBn;
            int li  = (tid < 64) ? tid : (tid - 64);
            CP_ASYNC4(sb + SM_H0 + (uint32_t)(buf^1)*512u + (uint32_t)(tid < 64 ? 0 : 256) + li*4,
                      (const char*)&g_h0v[(size_t)ray*128 + li*2]);
            CP_COMMIT();
        }

        // sample ids: [block][rowhalf]
        int s00 = mbase + 32*w + g;
        int s01 = s00 + 8;
        int s10 = s00 + 16;
        int s11 = s00 + 24;
        int r00 = s00 / PSTEPS, r01 = s01 / PSTEPS;
        int r10 = s10 / PSTEPS, r11 = s11 / PSTEPS;
        int rAc = mbase / PSTEPS;
        const __half* h0sb = (const __half*)(smem + SM_H0 + (uint32_t)buf*512u);
        const __half* hp[2][2] = {
            { h0sb + ((r00 != rAc) ? 128 : 0), h0sb + ((r01 != rAc) ? 128 : 0) },
            { h0sb + ((r10 != rAc) ? 128 : 0), h0sb + ((r11 != rAc) ? 128 : 0) } };

        // ---- layer 0: K=16 -> A1 frags in registers ----
        uint32_t aA = sb + SM_A0 + (uint32_t)buf*6144u + rowA*48 + colA;
        uint32_t a0f[2][4];
        LDSM_X4(a0f[0][0],a0f[0][1],a0f[0][2],a0f[0][3], aA);
        LDSM_X4(a0f[1][0],a0f[1][1],a0f[1][2],a0f[1][3], aA + 768);

        uint32_t aF[2][8][4];
        #pragma unroll
        for (int p = 0; p < 8; p++) {
            float cc[2][2][4];
            #pragma unroll
            for (int b = 0; b < 2; b++)
                #pragma unroll
                for (int hh = 0; hh < 2; hh++)
                    cc[b][hh][0]=cc[b][hh][1]=cc[b][hh][2]=cc[b][hh][3]=0.f;
            uint32_t bb0,bb1,bb2,bb3;
            LDSM_X4(bb0,bb1,bb2,bb3, aB0 + p*768);
            #pragma unroll
            for (int b = 0; b < 2; b++) {
                MMA_F16(cc[b][0], a0f[b][0],a0f[b][1],a0f[b][2],a0f[b][3], bb0,bb1);
                MMA_F16(cc[b][1], a0f[b][0],a0f[b][1],a0f[b][2],a0f[b][3], bb2,bb3);
            }
            #pragma unroll
            for (int b = 0; b < 2; b++)
                #pragma unroll
                for (int hh = 0; hh < 2; hh++) {
                    const float* c4 = cc[b][hh];
                    int col = p*16 + hh*8 + tg*2;
                    float2 hA = __half22float2(*(const __half2*)&hp[b][0][col]);
                    float2 hB = __half22float2(*(const __half2*)&hp[b][1][col]);
                    float f00 = fmaxf(c4[0] + hA.x, 0.f);
                    float f01 = fmaxf(c4[1] + hA.y, 0.f);
                    float f10 = fmaxf(c4[2] + hB.x, 0.f);
                    float f11 = fmaxf(c4[3] + hB.y, 0.f);
                    aF[b][p][0+hh*2] = pack_h2(f00, f01);
                    aF[b][p][1+hh*2] = pack_h2(f10, f11);
                }
        }

        // ---- layer 1 (K=128) + fused layer 2 MMA per 16-col chunk ----
        float c2[2][4];
        c2[0][0]=c2[0][1]=c2[0][2]=c2[0][3]=0.f;
        c2[1][0]=c2[1][1]=c2[1][2]=c2[1][3]=0.f;

        #pragma unroll
        for (int p = 0; p < 8; p++) {
            float cc[2][2][4];
            #pragma unroll
            for (int b = 0; b < 2; b++)
                #pragma unroll
                for (int hh = 0; hh < 2; hh++)
                    cc[b][hh][0]=cc[b][hh][1]=cc[b][hh][2]=cc[b][hh][3]=0.f;
            #pragma unroll
            for (int ks = 0; ks < 8; ks++) {
                uint32_t bb0,bb1,bb2,bb3;
                LDSM_X4(bb0,bb1,bb2,bb3, aB1 + p*4352 + ks*32);
                #pragma unroll
                for (int b = 0; b < 2; b++) {
                    MMA_F16(cc[b][0], aF[b][ks][0],aF[b][ks][1],aF[b][ks][2],aF[b][ks][3], bb0,bb1);
                    MMA_F16(cc[b][1], aF[b][ks][0],aF[b][ks][1],aF[b][ks][2],aF[b][ks][3], bb2,bb3);
                }
            }
            // bias + relu + pack -> layer2 A frag; accumulate layer2 MMA (k-chunk = p)
            #pragma unroll
            for (int b = 0; b < 2; b++) {
                uint32_t hf[4];
                #pragma unroll
                for (int hh = 0; hh < 2; hh++) {
                    const float* c4 = cc[b][hh];
                    int col = p*16 + hh*8 + tg*2;
                    float f0 = fmaxf(c4[0] + b1s[col],   0.f);
                    float f1 = fmaxf(c4[1] + b1s[col+1], 0.f);
                    float f2 = fmaxf(c4[2] + b1s[col],   0.f);
                    float f3 = fmaxf(c4[3] + b1s[col+1], 0.f);
                    hf[0+hh*2] = pack_h2(f0, f1);
                    hf[1+hh*2] = pack_h2(f2, f3);
                }
                MMA_F16(c2[b], hf[0],hf[1],hf[2],hf[3], b2f[p][0], b2f[p][1]);
            }
        }

        // ---- epilogue: sigmoid + weighted atomic, direct from c2 fragments ----
        if (tg == 0) {
            #pragma unroll
            for (int b = 0; b < 2; b++) {
                int sA = (b == 0) ? s00 : s10;
                int sB = (b == 0) ? s01 : s11;
                int rA_ = (b == 0) ? r00 : r10;
                int rB_ = (b == 0) ? r01 : r11;
                float wgA = g_w[sA], wgB = g_w[sB];
                atomicAdd(&out[rA_*3+0], wgA / (1.0f + __expf(-(c2[b][0] + b2r0))));
                atomicAdd(&out[rA_*3+1], wgA / (1.0f + __expf(-(c2[b][1] + b2r1))));
                atomicAdd(&out[rB_*3+0], wgB / (1.0f + __expf(-(c2[b][2] + b2r0))));
                atomicAdd(&out[rB_*3+1], wgB / (1.0f + __expf(-(c2[b][3] + b2r1))));
            }
        } else if (tg == 1) {
            #pragma unroll
            for (int b = 0; b < 2; b++) {
                int sA = (b == 0) ? s00 : s10;
                int sB = (b == 0) ? s01 : s11;
                int rA_ = (b == 0) ? r00 : r10;
                int rB_ = (b == 0) ? r01 : r11;
                float wgA = g_w[sA], wgB = g_w[sB];
                atomicAdd(&out[rA_*3+2], wgA / (1.0f + __expf(-(c2[b][0] + b2r2))));
                atomicAdd(&out[rB_*3+2], wgB / (1.0f + __expf(-(c2[b][2] + b2r2))));
            }
        }

        if (hn) CP_WAIT0();
        __syncthreads();
        buf ^= 1;
    }
}

// ---------------- launcher ----------------
extern "C" void kernel_launch(void* const* d_in, const int* in_sizes, int n_in,
                              void* d_out, int out_size)
{
    const float* rays_o   = (const float*)d_in[0];
    const float* rays_d   = (const float*)d_in[1];
    const float* viewdirs = (const float*)d_in[2];
    const float* dgrid    = (const float*)d_in[3];
    const float* k0g      = (const float*)d_in[4];
    const float* w0 = (const float*)d_in[5];
    const float* b0 = (const float*)d_in[6];
    const float* w1 = (const float*)d_in[7];
    const float* b1 = (const float*)d_in[8];
    const float* w2 = (const float*)d_in[9];
    const float* b2 = (const float*)d_in[10];
    const int* stepsize = (const int*)d_in[11];
    float* out = (float*)d_out;

    cudaFuncSetAttribute(k_mlp, cudaFuncAttributeMaxDynamicSharedMemorySize, SMEM_TOTAL);

    k_pack<<<(S3 + 255) / 256, 256>>>(dgrid, k0g);
    k_sample<<<(MTOT + 255) / 256, 256>>>(rays_o, rays_d, stepsize);
    k_scan<<<(N_RAYS * 32 + 255) / 256, 256>>>(viewdirs, out);
    k_h0v<<<(N_RAYS * 128) / 256, 256>>>(w0, b0);
    k_mlp<<<GRID_MLP, 128, SMEM_TOTAL>>>(w0, b0, w1, b1, w2, b2, out);
}

// round 11
// speedup vs baseline: 1.1303x; 1.0399x over previous
#include <cuda_runtime.h>
#include <cuda_fp16.h>
#include <math.h>
#include <stdint.h>

#define N_RAYS   4096
#define PSTEPS   254
#define P_INNER  231
#define MTOT     (N_RAYS*PSTEPS)      // 1,040,384
#define NTILES   (MTOT/128)           // 8128
#define WORLD    160
#define S2       (WORLD*WORLD)
#define S3       (WORLD*WORLD*WORLD)
#define ACT_SHIFT (-9.210240371976183f)
#define BG_LEN   0.2f
#define GRID_MLP 592                  // 4 CTAs per SM

// ---------------- scratch ----------------
__device__ uint4    g_pack[S3*2];       // per-voxel record: 12 fp16 k0 + fp32 density + pad (32 B)
__device__ uint16_t g_f16[MTOT*16];     // k0 features fp16 rows (12 real + 4 pad)
__device__ float    g_vembf[N_RAYS*27]; // view embedding fp32
__device__ uint16_t g_h0v[N_RAYS*128];  // per-ray layer0 contribution of vemb + b0 (fp16)
__device__ float    g_w[MTOT];

// ---------------- helpers ----------------
__device__ __forceinline__ uint16_t f2h(float f) {
    return __half_as_ushort(__float2half_rn(f));
}
__device__ __forceinline__ uint32_t pack_h2(float f0, float f1) {   // f0 -> low half
    __half2 v = __floats2half2_rn(f0, f1);
    return *reinterpret_cast<uint32_t*>(&v);
}
__device__ __forceinline__ uint32_t smem_u32(const void* p) {
    uint32_t a;
    asm("{ .reg .u64 t; cvta.to.shared.u64 t, %1; cvt.u32.u64 %0, t; }" : "=r"(a) : "l"(p));
    return a;
}

#define LDSM_X4(r0,r1,r2,r3,addr) \
    asm volatile("ldmatrix.sync.aligned.m8n8.x4.shared.b16 {%0,%1,%2,%3}, [%4];" \
        : "=r"(r0), "=r"(r1), "=r"(r2), "=r"(r3) : "r"(addr))

#define LDSM_X2(r0,r1,addr) \
    asm volatile("ldmatrix.sync.aligned.m8n8.x2.shared.b16 {%0,%1}, [%2];" \
        : "=r"(r0), "=r"(r1) : "r"(addr))

#define MMA_F16(c, a0,a1,a2,a3, b0,b1) \
    asm volatile("mma.sync.aligned.m16n8k16.row.col.f32.f16.f16.f32 " \
        "{%0,%1,%2,%3}, {%4,%5,%6,%7}, {%8,%9}, {%0,%1,%2,%3};" \
        : "+f"((c)[0]), "+f"((c)[1]), "+f"((c)[2]), "+f"((c)[3]) \
        : "r"(a0), "r"(a1), "r"(a2), "r"(a3), "r"(b0), "r"(b1))

#define CP_ASYNC16(dst, src) \
    asm volatile("cp.async.cg.shared.global [%0], [%1], 16;" :: "r"(dst), "l"(src) : "memory")
#define CP_ASYNC4(dst, src) \
    asm volatile("cp.async.ca.shared.global [%0], [%1], 4;" :: "r"(dst), "l"(src) : "memory")
#define CP_COMMIT() asm volatile("cp.async.commit_group;" ::: "memory")
#define CP_WAIT0()  asm volatile("cp.async.wait_group 0;" ::: "memory")

// ---------------- K0: grid repack (channel-interleaved 32B records) ----------------
__global__ void k_pack(const float* __restrict__ dgrid, const float* __restrict__ k0g)
{
    int idx = blockIdx.x * blockDim.x + threadIdx.x;
    if (idx >= S3) return;
    uint32_t h[6];
    #pragma unroll
    for (int c = 0; c < 6; c++)
        h[c] = pack_h2(__ldg(&k0g[(2*c)*S3 + idx]), __ldg(&k0g[(2*c+1)*S3 + idx]));
    float d = __ldg(&dgrid[idx]);
    g_pack[(size_t)idx*2+0] = make_uint4(h[0], h[1], h[2], h[3]);
    g_pack[(size_t)idx*2+1] = make_uint4(h[4], h[5], __float_as_uint(d), 0u);
}

// ---------------- K1: warp-per-ray sampling + interp + vemb + transmittance scan ----------------
__global__ void k_sample(const float* __restrict__ ro, const float* __restrict__ rdir,
                         const float* __restrict__ vdirs, const int* __restrict__ stepsize,
                         float* __restrict__ out)
{
    int gw = (blockIdx.x * blockDim.x + threadIdx.x) >> 5;   // ray id
    int lane = threadIdx.x & 31;
    if (gw >= N_RAYS) return;

    // view embedding (raw viewdirs)
    float v0 = __ldg(&vdirs[gw*3+0]);
    float v1 = __ldg(&vdirs[gw*3+1]);
    float v2 = __ldg(&vdirs[gw*3+2]);
    if (lane < 27) {
        float v;
        if (lane < 3) {
            v = (lane == 0) ? v0 : (lane == 1) ? v1 : v2;
        } else {
            int kk = (lane < 15) ? (lane - 3) : (lane - 15);
            int c = kk >> 2, e = kk & 3;
            float dc = (c == 0) ? v0 : (c == 1) ? v1 : v2;
            float vv = dc * (float)(1 << e);
            v = (lane < 15) ? sinf(vv) : cosf(vv);
        }
        g_vembf[gw*27 + lane] = v;
    }

    // normalized ray direction + origin
    float dx = __ldg(&rdir[gw*3+0]), dy = __ldg(&rdir[gw*3+1]), dz = __ldg(&rdir[gw*3+2]);
    float inv = rsqrtf(dx*dx + dy*dy + dz*dz);
    dx *= inv; dy *= inv; dz *= inv;
    float ox = __ldg(&ro[gw*3+0]), oy = __ldg(&ro[gw*3+1]), oz = __ldg(&ro[gw*3+2]);

    int sv = *stepsize;
    float interval = (sv > 0 && sv < 1000000) ? (float)sv : __int_as_float(sv);

    float T = 1.0f;
    int base = gw * PSTEPS;
    const float SQ3x2 = 3.4641016151377546f;

    #pragma unroll 1
    for (int chunk = 0; chunk < 8; chunk++) {
        int p = chunk*32 + lane;
        bool valid = p < PSTEPS;
        int pe = valid ? p : (PSTEPS - 1);

        float t;
        if (pe < P_INNER) {
            t = SQ3x2 * ((float)pe + 0.5f) * (1.0f / 231.0f);
        } else {
            int q = pe - P_INNER;
            float L0 = 1.0f - (float)q     * (0.999f / 23.0f);
            float L1 = 1.0f - (float)(q+1) * (0.999f / 23.0f);
            t = 0.5f * SQ3x2 * (1.0f / L0 + 1.0f / L1);
        }

        float px = ox + dx * t, py = oy + dy * t, pz = oz + dz * t;
        float nm = fmaxf(fabsf(px), fmaxf(fabsf(py), fabsf(pz)));
        if (nm > 1.0f) {
            float sc = (1.0f + BG_LEN - BG_LEN / nm) / nm;
            px *= sc; py *= sc; pz *= sc;
        }

        const float GS = 159.0f / 2.4f;
        float gx = fminf(fmaxf((px + 1.2f) * GS, 0.0f), 159.0f);
        float gy = fminf(fmaxf((py + 1.2f) * GS, 0.0f), 159.0f);
        float gz = fminf(fmaxf((pz + 1.2f) * GS, 0.0f), 159.0f);
        int ix = min((int)gx, 158);
        int iy = min((int)gy, 158);
        int iz = min((int)gz, 158);
        float fx = gx - (float)ix, fy = gy - (float)iy, fz = gz - (float)iz;

        int vb = (ix * WORLD + iy) * WORLD + iz;
        float w00 = (1.f-fx)*(1.f-fy), w01 = (1.f-fx)*fy, w10 = fx*(1.f-fy), w11 = fx*fy;
        float wz0 = 1.f - fz, wz1 = fz;

        float wt[8];
        wt[0]=w00*wz0; wt[1]=w00*wz1; wt[2]=w01*wz0; wt[3]=w01*wz1;
        wt[4]=w10*wz0; wt[5]=w10*wz1; wt[6]=w11*wz0; wt[7]=w11*wz1;
        int off[8];
        off[0]=vb;          off[1]=vb+1;
        off[2]=vb+WORLD;    off[3]=vb+WORLD+1;
        off[4]=vb+S2;       off[5]=vb+S2+1;
        off[6]=vb+S2+WORLD; off[7]=vb+S2+WORLD+1;

        float acc[12];
        #pragma unroll
        for (int c = 0; c < 12; c++) acc[c] = 0.0f;
        float dsum = 0.0f;

        #pragma unroll
        for (int u = 0; u < 8; u++) {
            const uint4* rec = &g_pack[(size_t)off[u]*2];
            uint4 qa = __ldg(&rec[0]);
            uint4 qb = __ldg(&rec[1]);
            float wtu = wt[u];
            float2 f;
            f = __half22float2(*(const __half2*)&qa.x); acc[0] += wtu*f.x; acc[1] += wtu*f.y;
            f = __half22float2(*(const __half2*)&qa.y); acc[2] += wtu*f.x; acc[3] += wtu*f.y;
            f = __half22float2(*(const __half2*)&qa.z); acc[4] += wtu*f.x; acc[5] += wtu*f.y;
            f = __half22float2(*(const __half2*)&qa.w); acc[6] += wtu*f.x; acc[7] += wtu*f.y;
            f = __half22float2(*(const __half2*)&qb.x); acc[8] += wtu*f.x; acc[9] += wtu*f.y;
            f = __half22float2(*(const __half2*)&qb.y); acc[10]+= wtu*f.x; acc[11]+= wtu*f.y;
            dsum += wtu * __uint_as_float(qb.z);
        }

        float x = dsum + ACT_SHIFT;
        float sp = (x > 20.0f) ? x : log1pf(expf(x));
        float alpha = valid ? (1.0f - expf(-interval * sp)) : 0.0f;

        // feature row out
        if (valid) {
            uint32_t ph[8];
            #pragma unroll
            for (int c = 0; c < 6; c++) ph[c] = pack_h2(acc[2*c], acc[2*c+1]);
            ph[6] = ph[7] = 0u;
            uint4* dh = (uint4*)&g_f16[(size_t)(base + p)*16];
            dh[0] = make_uint4(ph[0],ph[1],ph[2],ph[3]);
            dh[1] = make_uint4(ph[4],ph[5],ph[6],ph[7]);
        }

        // inclusive shfl scan of (1-alpha), exclusive weight
        float q = 1.0f - alpha;
        float incl = q;
        #pragma unroll
        for (int dlt = 1; dlt < 32; dlt <<= 1) {
            float o = __shfl_up_sync(0xffffffffu, incl, dlt);
            if (lane >= dlt) incl *= o;
        }
        float excl = __shfl_up_sync(0xffffffffu, incl, 1);
        if (lane == 0) excl = 1.0f;
        if (valid) g_w[base + p] = alpha * T * excl;
        float tot = __shfl_sync(0xffffffffu, incl, 31);
        T *= tot;
    }
    if (lane == 0) {
        out[gw*3+0] = T; out[gw*3+1] = T; out[gw*3+2] = T;   // BG = 1.0
    }
}

// ---------------- K2b: per-ray layer0 view contribution (fp16): h0v = b0 + vemb @ W0[12:39] ----------------
__global__ void k_h0v(const float* __restrict__ w0, const float* __restrict__ b0)
{
    int gid = blockIdx.x * blockDim.x + threadIdx.x;
    int r = gid >> 7, n = gid & 127;
    float acc = __ldg(&b0[n]);
    #pragma unroll
    for (int k = 0; k < 27; k++)
        acc = fmaf(g_vembf[r*27 + k], __ldg(&w0[(12+k)*128 + n]), acc);
    g_h0v[r*128 + n] = f2h(acc);
}

// ---------------- K3: persistent fp16 mma.sync MLP (layer2 as MMA), 128 thr, 4 CTAs/SM ----------------
// smem layout (bytes)
#define SM_B1V   0        // 512:   b1 as half2[64] (256 B used)
#define SM_H0    512      // 1024:  [2 buf][2 rays][128 half]
#define SM_A0    1536     // 12288: [2 buf][128 rows][48 B]
#define SM_B0    13824    // 6144:  [128 n][48 B] (k 0..15 real)
#define SM_B1    19968    // 34816: [128 n][272 B] (k 0..127 real)
#define SM_B2    54784    // 2176:  [8 n][272 B] (n 0..2 real)
#define SMEM_TOTAL 56960

__global__ void __launch_bounds__(128, 4) k_mlp(
    const float* __restrict__ w0, const float* __restrict__ b0,
    const float* __restrict__ w1, const float* __restrict__ b1,
    const float* __restrict__ w2, const float* __restrict__ b2,
    float* __restrict__ out)
{
    extern __shared__ unsigned char smem[];
    uint32_t sb = smem_u32(smem);
    int tid = threadIdx.x;
    int w = tid >> 5, l = tid & 31;
    int g = l >> 2, tg = l & 3;

    // ---- one-time weight staging (fp16, [n][k] layout) ----
    if (tid < 64) ((uint32_t*)(smem + SM_B1V))[tid] = pack_h2(b1[2*tid], b1[2*tid+1]);

    for (int idx = tid; idx < 128*16; idx += 128) {
        int n = idx & 127, k = idx >> 7;
        float v = (k < 12) ? w0[k*128 + n] : 0.0f;
        *(uint16_t*)(smem + SM_B0 + n*48 + k*2) = f2h(v);
    }
    for (int idx = tid; idx < 128*128; idx += 128) {
        int n = idx & 127, k = idx >> 7;
        *(uint16_t*)(smem + SM_B1 + n*272 + k*2) = f2h(w1[k*128 + n]);
    }
    for (int idx = tid; idx < 8*128; idx += 128) {
        int n = idx & 7, k = idx >> 3;
        float v = (n < 3) ? w2[k*3 + n] : 0.0f;
        *(uint16_t*)(smem + SM_B2 + n*272 + k*2) = f2h(v);
    }
    float b2r0 = __ldg(&b2[0]), b2r1 = __ldg(&b2[1]), b2r2 = __ldg(&b2[2]);
    const __half2* b1h2 = (const __half2*)(smem + SM_B1V);
    const __half2 hz = __floats2half2_rn(0.f, 0.f);

    // ---- lane-invariant ldmatrix addresses ----
    uint32_t rowA = 32u*w + (l & 7) + ((l >> 3) & 1) * 8;   // block 0; block 1 = +16 rows (768B)
    uint32_t colA = (uint32_t)(l >> 4) * 16;
    uint32_t lrow = (l & 7) + ((l >> 4) & 1) * 8;
    uint32_t lcol = ((l >> 3) & 1) * 16;
    uint32_t aB0 = sb + SM_B0 + lrow*48  + lcol;
    uint32_t aB1 = sb + SM_B1 + lrow*272 + lcol;
    uint32_t aB2 = sb + SM_B2 + (uint32_t)(l & 7)*272 + ((l >> 3) & 1)*16;

    int srow = tid;   // each thread stages one full row (32 B)
    uint32_t a0dst0 = sb + SM_A0 + srow*48;

    // ---- prime A0 + H0 buffer 0 (cp.async) ----
    int m = blockIdx.x;
    if (m < NTILES) {
        const char* src = (const char*)&g_f16[(size_t)(m*128+srow)*16];
        CP_ASYNC16(a0dst0,      src);
        CP_ASYNC16(a0dst0 + 16, src + 16);
        int rA = (m*128) / PSTEPS;
        int rB = (m*128 + 127) / PSTEPS;
        int ray = (tid < 64) ? rA : rB;
        int li  = (tid < 64) ? tid : (tid - 64);
        CP_ASYNC4(sb + SM_H0 + (uint32_t)(tid < 64 ? 0 : 256) + li*4,
                  (const char*)&g_h0v[(size_t)ray*128 + li*2]);
        CP_COMMIT();
        CP_WAIT0();
    }
    __syncthreads();

    // ---- preload layer-2 B fragments (tile-invariant) ----
    uint32_t b2f[8][2];
    #pragma unroll
    for (int p = 0; p < 8; p++) LDSM_X2(b2f[p][0], b2f[p][1], aB2 + p*32);

    int buf = 0;

    for (; m < NTILES; m += gridDim.x) {
        int mbase = m * 128;
        int mn = m + gridDim.x;
        bool hn = mn < NTILES;
        if (hn) {   // async-stage next tile into alternate buffer (hidden under compute)
            uint32_t ab = a0dst0 + (uint32_t)(buf^1)*6144u;
            const char* src = (const char*)&g_f16[(size_t)(mn*128+srow)*16];
            CP_ASYNC16(ab,      src);
            CP_ASYNC16(ab + 16, src + 16);
            int rAn = (mn*128) / PSTEPS;
            int rBn = (mn*128 + 127) / PSTEPS;
            int ray = (tid < 64) ? rAn : rBn;
            int li  = (tid < 64) ? tid : (tid - 64);
            CP_ASYNC4(sb + SM_H0 + (uint32_t)(buf^1)*512u + (uint32_t)(tid < 64 ? 0 : 256) + li*4,
                      (const char*)&g_h0v[(size_t)ray*128 + li*2]);
            CP_COMMIT();
        }

        // sample ids: [block][rowhalf]
        int s00 = mbase + 32*w + g;
        int s01 = s00 + 8;
        int s10 = s00 + 16;
        int s11 = s00 + 24;
        int r00 = s00 / PSTEPS, r01 = s01 / PSTEPS;
        int r10 = s10 / PSTEPS, r11 = s11 / PSTEPS;
        int rAc = mbase / PSTEPS;
        const __half* h0sb = (const __half*)(smem + SM_H0 + (uint32_t)buf*512u);
        const __half* hp[2][2] = {
            { h0sb + ((r00 != rAc) ? 128 : 0), h0sb + ((r01 != rAc) ? 128 : 0) },
            { h0sb + ((r10 != rAc) ? 128 : 0), h0sb + ((r11 != rAc) ? 128 : 0) } };

        // ---- layer 0: K=16 -> A1 frags in registers (half2 epilogue) ----
        uint32_t aA = sb + SM_A0 + (uint32_t)buf*6144u + rowA*48 + colA;
        uint32_t a0f[2][4];
        LDSM_X4(a0f[0][0],a0f[0][1],a0f[0][2],a0f[0][3], aA);
        LDSM_X4(a0f[1][0],a0f[1][1],a0f[1][2],a0f[1][3], aA + 768);

        uint32_t aF[2][8][4];
        #pragma unroll
        for (int p = 0; p < 8; p++) {
            float cc[2][2][4];
            #pragma unroll
            for (int b = 0; b < 2; b++)
                #pragma unroll
                for (int hh = 0; hh < 2; hh++)
                    cc[b][hh][0]=cc[b][hh][1]=cc[b][hh][2]=cc[b][hh][3]=0.f;
            uint32_t bb0,bb1,bb2,bb3;
            LDSM_X4(bb0,bb1,bb2,bb3, aB0 + p*768);
            #pragma unroll
            for (int b = 0; b < 2; b++) {
                MMA_F16(cc[b][0], a0f[b][0],a0f[b][1],a0f[b][2],a0f[b][3], bb0,bb1);
                MMA_F16(cc[b][1], a0f[b][0],a0f[b][1],a0f[b][2],a0f[b][3], bb2,bb3);
            }
            #pragma unroll
            for (int b = 0; b < 2; b++)
                #pragma unroll
                for (int hh = 0; hh < 2; hh++) {
                    const float* c4 = cc[b][hh];
                    int col = p*16 + hh*8 + tg*2;
                    __half2 ch0 = __floats2half2_rn(c4[0], c4[1]);
                    __half2 ch1 = __floats2half2_rn(c4[2], c4[3]);
                    __half2 hA = *(const __half2*)&hp[b][0][col];
                    __half2 hB = *(const __half2*)&hp[b][1][col];
                    __half2 o0 = __hmax2(__hadd2(ch0, hA), hz);
                    __half2 o1 = __hmax2(__hadd2(ch1, hB), hz);
                    aF[b][p][0+hh*2] = *(uint32_t*)&o0;
                    aF[b][p][1+hh*2] = *(uint32_t*)&o1;
                }
        }

        // ---- layer 1 (K=128) + fused layer 2 MMA per 16-col chunk (half2 epilogue) ----
        float c2[2][4];
        c2[0][0]=c2[0][1]=c2[0][2]=c2[0][3]=0.f;
        c2[1][0]=c2[1][1]=c2[1][2]=c2[1][3]=0.f;

        #pragma unroll
        for (int p = 0; p < 8; p++) {
            float cc[2][2][4];
            #pragma unroll
            for (int b = 0; b < 2; b++)
                #pragma unroll
                for (int hh = 0; hh < 2; hh++)
                    cc[b][hh][0]=cc[b][hh][1]=cc[b][hh][2]=cc[b][hh][3]=0.f;
            #pragma unroll
            for (int ks = 0; ks < 8; ks++) {
                uint32_t bb0,bb1,bb2,bb3;
                LDSM_X4(bb0,bb1,bb2,bb3, aB1 + p*4352 + ks*32);
                #pragma unroll
                for (int b = 0; b < 2; b++) {
                    MMA_F16(cc[b][0], aF[b][ks][0],aF[b][ks][1],aF[b][ks][2],aF[b][ks][3], bb0,bb1);
                    MMA_F16(cc[b][1], aF[b][ks][0],aF[b][ks][1],aF[b][ks][2],aF[b][ks][3], bb2,bb3);
                }
            }
            // bias + relu + pack -> layer2 A frag; accumulate layer2 MMA (k-chunk = p)
            #pragma unroll
            for (int b = 0; b < 2; b++) {
                uint32_t hf[4];
                #pragma unroll
                for (int hh = 0; hh < 2; hh++) {
                    const float* c4 = cc[b][hh];
                    int col = p*16 + hh*8 + tg*2;
                    __half2 bh = b1h2[col >> 1];
                    __half2 ch0 = __floats2half2_rn(c4[0], c4[1]);
                    __half2 ch1 = __floats2half2_rn(c4[2], c4[3]);
                    __half2 o0 = __hmax2(__hadd2(ch0, bh), hz);
                    __half2 o1 = __hmax2(__hadd2(ch1, bh), hz);
                    hf[0+hh*2] = *(uint32_t*)&o0;
                    hf[1+hh*2] = *(uint32_t*)&o1;
                }
                MMA_F16(c2[b], hf[0],hf[1],hf[2],hf[3], b2f[p][0], b2f[p][1]);
            }
        }

        // ---- epilogue: sigmoid + weighted atomic, direct from c2 fragments ----
        if (tg == 0) {
            #pragma unroll
            for (int b = 0; b < 2; b++) {
                int sA = (b == 0) ? s00 : s10;
                int sB = (b == 0) ? s01 : s11;
                int rA_ = (b == 0) ? r00 : r10;
                int rB_ = (b == 0) ? r01 : r11;
                float wgA = g_w[sA], wgB = g_w[sB];
                atomicAdd(&out[rA_*3+0], wgA / (1.0f + __expf(-(c2[b][0] + b2r0))));
                atomicAdd(&out[rA_*3+1], wgA / (1.0f + __expf(-(c2[b][1] + b2r1))));
                atomicAdd(&out[rB_*3+0], wgB / (1.0f + __expf(-(c2[b][2] + b2r0))));
                atomicAdd(&out[rB_*3+1], wgB / (1.0f + __expf(-(c2[b][3] + b2r1))));
            }
        } else if (tg == 1) {
            #pragma unroll
            for (int b = 0; b < 2; b++) {
                int sA = (b == 0) ? s00 : s10;
                int sB = (b == 0) ? s01 : s11;
                int rA_ = (b == 0) ? r00 : r10;
                int rB_ = (b == 0) ? r01 : r11;
                float wgA = g_w[sA], wgB = g_w[sB];
                atomicAdd(&out[rA_*3+2], wgA / (1.0f + __expf(-(c2[b][0] + b2r2))));
                atomicAdd(&out[rB_*3+2], wgB / (1.0f + __expf(-(c2[b][2] + b2r2))));
            }
        }

        if (hn) CP_WAIT0();
        __syncthreads();
        buf ^= 1;
    }
}

// ---------------- launcher ----------------
extern "C" void kernel_launch(void* const* d_in, const int* in_sizes, int n_in,
                              void* d_out, int out_size)
{
    const float* rays_o   = (const float*)d_in[0];
    const float* rays_d   = (const float*)d_in[1];
    const float* viewdirs = (const float*)d_in[2];
    const float* dgrid    = (const float*)d_in[3];
    const float* k0g      = (const float*)d_in[4];
    const float* w0 = (const float*)d_in[5];
    const float* b0 = (const float*)d_in[6];
    const float* w1 = (const float*)d_in[7];
    const float* b1 = (const float*)d_in[8];
    const float* w2 = (const float*)d_in[9];
    const float* b2 = (const float*)d_in[10];
    const int* stepsize = (const int*)d_in[11];
    float* out = (float*)d_out;

    cudaFuncSetAttribute(k_mlp, cudaFuncAttributeMaxDynamicSharedMemorySize, SMEM_TOTAL);

    k_pack<<<(S3 + 255) / 256, 256>>>(dgrid, k0g);
    k_sample<<<(N_RAYS * 32 + 255) / 256, 256>>>(rays_o, rays_d, viewdirs, stepsize, out);
    k_h0v<<<(N_RAYS * 128) / 256, 256>>>(w0, b0);
    k_mlp<<<GRID_MLP, 128, SMEM_TOTAL>>>(w0, b0, w1, b1, w2, b2, out);
}

// round 12
// speedup vs baseline: 1.1978x; 1.0597x over previous
#include <cuda_runtime.h>
#include <cuda_fp16.h>
#include <math.h>
#include <stdint.h>

#define N_RAYS   4096
#define PSTEPS   254
#define P_INNER  231
#define MTOT     (N_RAYS*PSTEPS)      // 1,040,384
#define NTILES   (MTOT/128)           // 8128
#define WORLD    160
#define S2       (WORLD*WORLD)
#define S3       (WORLD*WORLD*WORLD)
#define ACT_SHIFT (-9.210240371976183f)
#define BG_LEN   0.2f
#define GRID_MLP 592                  // 4 CTAs per SM

// ---------------- scratch ----------------
__device__ uint4    g_pack[S3*2];       // per-voxel record: 12 fp16 k0 + fp32 density + pad (32 B)
__device__ uint16_t g_f16[MTOT*16];     // k0 features fp16 rows (12 real + 4 pad)
__device__ float    g_vembf[N_RAYS*27]; // view embedding fp32
__device__ uint16_t g_h0v[N_RAYS*128];  // per-ray layer0 contribution of vemb + b0 (fp16)
__device__ float    g_w[MTOT];

// ---------------- helpers ----------------
__device__ __forceinline__ uint16_t f2h(float f) {
    return __half_as_ushort(__float2half_rn(f));
}
__device__ __forceinline__ uint32_t pack_h2(float f0, float f1) {   // f0 -> low half
    __half2 v = __floats2half2_rn(f0, f1);
    return *reinterpret_cast<uint32_t*>(&v);
}
__device__ __forceinline__ uint32_t smem_u32(const void* p) {
    uint32_t a;
    asm("{ .reg .u64 t; cvta.to.shared.u64 t, %1; cvt.u32.u64 %0, t; }" : "=r"(a) : "l"(p));
    return a;
}

#define LDSM_X4(r0,r1,r2,r3,addr) \
    asm volatile("ldmatrix.sync.aligned.m8n8.x4.shared.b16 {%0,%1,%2,%3}, [%4];" \
        : "=r"(r0), "=r"(r1), "=r"(r2), "=r"(r3) : "r"(addr))

#define LDSM_X2(r0,r1,addr) \
    asm volatile("ldmatrix.sync.aligned.m8n8.x2.shared.b16 {%0,%1}, [%2];" \
        : "=r"(r0), "=r"(r1) : "r"(addr))

// f32-accumulator MMA (layer 2 only)
#define MMA_F16(c, a0,a1,a2,a3, b0,b1) \
    asm volatile("mma.sync.aligned.m16n8k16.row.col.f32.f16.f16.f32 " \
        "{%0,%1,%2,%3}, {%4,%5,%6,%7}, {%8,%9}, {%0,%1,%2,%3};" \
        : "+f"((c)[0]), "+f"((c)[1]), "+f"((c)[2]), "+f"((c)[3]) \
        : "r"(a0), "r"(a1), "r"(a2), "r"(a3), "r"(b0), "r"(b1))

// f16-accumulator MMA (layers 0/1): D,C = 2x .f16x2 registers
#define MMA_F16H(c, a0,a1,a2,a3, b0,b1) \
    asm volatile("mma.sync.aligned.m16n8k16.row.col.f16.f16.f16.f16 " \
        "{%0,%1}, {%2,%3,%4,%5}, {%6,%7}, {%0,%1};" \
        : "+r"((c)[0]), "+r"((c)[1]) \
        : "r"(a0), "r"(a1), "r"(a2), "r"(a3), "r"(b0), "r"(b1))

#define CP_ASYNC16(dst, src) \
    asm volatile("cp.async.cg.shared.global [%0], [%1], 16;" :: "r"(dst), "l"(src) : "memory")
#define CP_ASYNC4(dst, src) \
    asm volatile("cp.async.ca.shared.global [%0], [%1], 4;" :: "r"(dst), "l"(src) : "memory")
#define CP_COMMIT() asm volatile("cp.async.commit_group;" ::: "memory")
#define CP_WAIT0()  asm volatile("cp.async.wait_group 0;" ::: "memory")

// ---------------- K0: grid repack (channel-interleaved 32B records) ----------------
__global__ void k_pack(const float* __restrict__ dgrid, const float* __restrict__ k0g)
{
    int idx = blockIdx.x * blockDim.x + threadIdx.x;
    if (idx >= S3) return;
    uint32_t h[6];
    #pragma unroll
    for (int c = 0; c < 6; c++)
        h[c] = pack_h2(__ldg(&k0g[(2*c)*S3 + idx]), __ldg(&k0g[(2*c+1)*S3 + idx]));
    float d = __ldg(&dgrid[idx]);
    g_pack[(size_t)idx*2+0] = make_uint4(h[0], h[1], h[2], h[3]);
    g_pack[(size_t)idx*2+1] = make_uint4(h[4], h[5], __float_as_uint(d), 0u);
}

// ---------------- K1: warp-per-ray sampling + interp + vemb + transmittance scan ----------------
__global__ void k_sample(const float* __restrict__ ro, const float* __restrict__ rdir,
                         const float* __restrict__ vdirs, const int* __restrict__ stepsize,
                         float* __restrict__ out)
{
    int gw = (blockIdx.x * blockDim.x + threadIdx.x) >> 5;   // ray id
    int lane = threadIdx.x & 31;
    if (gw >= N_RAYS) return;

    float v0 = __ldg(&vdirs[gw*3+0]);
    float v1 = __ldg(&vdirs[gw*3+1]);
    float v2 = __ldg(&vdirs[gw*3+2]);
    if (lane < 27) {
        float v;
        if (lane < 3) {
            v = (lane == 0) ? v0 : (lane == 1) ? v1 : v2;
        } else {
            int kk = (lane < 15) ? (lane - 3) : (lane - 15);
            int c = kk >> 2, e = kk & 3;
            float dc = (c == 0) ? v0 : (c == 1) ? v1 : v2;
            float vv = dc * (float)(1 << e);
            v = (lane < 15) ? sinf(vv) : cosf(vv);
        }
        g_vembf[gw*27 + lane] = v;
    }

    float dx = __ldg(&rdir[gw*3+0]), dy = __ldg(&rdir[gw*3+1]), dz = __ldg(&rdir[gw*3+2]);
    float inv = rsqrtf(dx*dx + dy*dy + dz*dz);
    dx *= inv; dy *= inv; dz *= inv;
    float ox = __ldg(&ro[gw*3+0]), oy = __ldg(&ro[gw*3+1]), oz = __ldg(&ro[gw*3+2]);

    int sv = *stepsize;
    float interval = (sv > 0 && sv < 1000000) ? (float)sv : __int_as_float(sv);

    float T = 1.0f;
    int base = gw * PSTEPS;
    const float SQ3x2 = 3.4641016151377546f;

    #pragma unroll 1
    for (int chunk = 0; chunk < 8; chunk++) {
        int p = chunk*32 + lane;
        bool valid = p < PSTEPS;
        int pe = valid ? p : (PSTEPS - 1);

        float t;
        if (pe < P_INNER) {
            t = SQ3x2 * ((float)pe + 0.5f) * (1.0f / 231.0f);
        } else {
            int q = pe - P_INNER;
            float L0 = 1.0f - (float)q     * (0.999f / 23.0f);
            float L1 = 1.0f - (float)(q+1) * (0.999f / 23.0f);
            t = 0.5f * SQ3x2 * (1.0f / L0 + 1.0f / L1);
        }

        float px = ox + dx * t, py = oy + dy * t, pz = oz + dz * t;
        float nm = fmaxf(fabsf(px), fmaxf(fabsf(py), fabsf(pz)));
        if (nm > 1.0f) {
            float sc = (1.0f + BG_LEN - BG_LEN / nm) / nm;
            px *= sc; py *= sc; pz *= sc;
        }

        const float GS = 159.0f / 2.4f;
        float gx = fminf(fmaxf((px + 1.2f) * GS, 0.0f), 159.0f);
        float gy = fminf(fmaxf((py + 1.2f) * GS, 0.0f), 159.0f);
        float gz = fminf(fmaxf((pz + 1.2f) * GS, 0.0f), 159.0f);
        int ix = min((int)gx, 158);
        int iy = min((int)gy, 158);
        int iz = min((int)gz, 158);
        float fx = gx - (float)ix, fy = gy - (float)iy, fz = gz - (float)iz;

        int vb = (ix * WORLD + iy) * WORLD + iz;
        float w00 = (1.f-fx)*(1.f-fy), w01 = (1.f-fx)*fy, w10 = fx*(1.f-fy), w11 = fx*fy;
        float wz0 = 1.f - fz, wz1 = fz;

        float wt[8];
        wt[0]=w00*wz0; wt[1]=w00*wz1; wt[2]=w01*wz0; wt[3]=w01*wz1;
        wt[4]=w10*wz0; wt[5]=w10*wz1; wt[6]=w11*wz0; wt[7]=w11*wz1;
        int off[8];
        off[0]=vb;          off[1]=vb+1;
        off[2]=vb+WORLD;    off[3]=vb+WORLD+1;
        off[4]=vb+S2;       off[5]=vb+S2+1;
        off[6]=vb+S2+WORLD; off[7]=vb+S2+WORLD+1;

        float acc[12];
        #pragma unroll
        for (int c = 0; c < 12; c++) acc[c] = 0.0f;
        float dsum = 0.0f;

        #pragma unroll
        for (int u = 0; u < 8; u++) {
            const uint4* rec = &g_pack[(size_t)off[u]*2];
            uint4 qa = __ldg(&rec[0]);
            uint4 qb = __ldg(&rec[1]);
            float wtu = wt[u];
            float2 f;
            f = __half22float2(*(const __half2*)&qa.x); acc[0] += wtu*f.x; acc[1] += wtu*f.y;
            f = __half22float2(*(const __half2*)&qa.y); acc[2] += wtu*f.x; acc[3] += wtu*f.y;
            f = __half22float2(*(const __half2*)&qa.z); acc[4] += wtu*f.x; acc[5] += wtu*f.y;
            f = __half22float2(*(const __half2*)&qa.w); acc[6] += wtu*f.x; acc[7] += wtu*f.y;
            f = __half22float2(*(const __half2*)&qb.x); acc[8] += wtu*f.x; acc[9] += wtu*f.y;
            f = __half22float2(*(const __half2*)&qb.y); acc[10]+= wtu*f.x; acc[11]+= wtu*f.y;
            dsum += wtu * __uint_as_float(qb.z);
        }

        float x = dsum + ACT_SHIFT;
        float sp = (x > 20.0f) ? x : log1pf(expf(x));
        float alpha = valid ? (1.0f - expf(-interval * sp)) : 0.0f;

        if (valid) {
            uint32_t ph[8];
            #pragma unroll
            for (int c = 0; c < 6; c++) ph[c] = pack_h2(acc[2*c], acc[2*c+1]);
            ph[6] = ph[7] = 0u;
            uint4* dh = (uint4*)&g_f16[(size_t)(base + p)*16];
            dh[0] = make_uint4(ph[0],ph[1],ph[2],ph[3]);
            dh[1] = make_uint4(ph[4],ph[5],ph[6],ph[7]);
        }

        float q = 1.0f - alpha;
        float incl = q;
        #pragma unroll
        for (int dlt = 1; dlt < 32; dlt <<= 1) {
            float o = __shfl_up_sync(0xffffffffu, incl, dlt);
            if (lane >= dlt) incl *= o;
        }
        float excl = __shfl_up_sync(0xffffffffu, incl, 1);
        if (lane == 0) excl = 1.0f;
        if (valid) g_w[base + p] = alpha * T * excl;
        float tot = __shfl_sync(0xffffffffu, incl, 31);
        T *= tot;
    }
    if (lane == 0) {
        out[gw*3+0] = T; out[gw*3+1] = T; out[gw*3+2] = T;   // BG = 1.0
    }
}

// ---------------- K2b: per-ray layer0 view contribution (fp16): h0v = b0 + vemb @ W0[12:39] ----------------
__global__ void k_h0v(const float* __restrict__ w0, const float* __restrict__ b0)
{
    int gid = blockIdx.x * blockDim.x + threadIdx.x;
    int r = gid >> 7, n = gid & 127;
    float acc = __ldg(&b0[n]);
    #pragma unroll
    for (int k = 0; k < 27; k++)
        acc = fmaf(g_vembf[r*27 + k], __ldg(&w0[(12+k)*128 + n]), acc);
    g_h0v[r*128 + n] = f2h(acc);
}

// ---------------- K3: persistent fp16-acc mma.sync MLP, 128 thr, 4 CTAs/SM ----------------
// smem layout (bytes)
#define SM_B1V   0        // 512:   b1 as half2[64] (256 B used)
#define SM_H0    512      // 1024:  [2 buf][2 rays][128 half]
#define SM_A0    1536     // 12288: [2 buf][128 rows][48 B]
#define SM_B0    13824    // 6144:  [128 n][48 B] (k 0..15 real)
#define SM_B1    19968    // 34816: [128 n][272 B] (k 0..127 real)
#define SM_B2    54784    // 2176:  [8 n][272 B] (n 0..2 real)
#define SMEM_TOTAL 56960

__global__ void __launch_bounds__(128, 4) k_mlp(
    const float* __restrict__ w0, const float* __restrict__ b0,
    const float* __restrict__ w1, const float* __restrict__ b1,
    const float* __restrict__ w2, const float* __restrict__ b2,
    float* __restrict__ out)
{
    extern __shared__ unsigned char smem[];
    uint32_t sb = smem_u32(smem);
    int tid = threadIdx.x;
    int w = tid >> 5, l = tid & 31;
    int g = l >> 2, tg = l & 3;

    // ---- one-time weight staging (fp16, [n][k] layout) ----
    if (tid < 64) ((uint32_t*)(smem + SM_B1V))[tid] = pack_h2(b1[2*tid], b1[2*tid+1]);

    for (int idx = tid; idx < 128*16; idx += 128) {
        int n = idx & 127, k = idx >> 7;
        float v = (k < 12) ? w0[k*128 + n] : 0.0f;
        *(uint16_t*)(smem + SM_B0 + n*48 + k*2) = f2h(v);
    }
    for (int idx = tid; idx < 128*128; idx += 128) {
        int n = idx & 127, k = idx >> 7;
        *(uint16_t*)(smem + SM_B1 + n*272 + k*2) = f2h(w1[k*128 + n]);
    }
    for (int idx = tid; idx < 8*128; idx += 128) {
        int n = idx & 7, k = idx >> 3;
        float v = (n < 3) ? w2[k*3 + n] : 0.0f;
        *(uint16_t*)(smem + SM_B2 + n*272 + k*2) = f2h(v);
    }
    float b2r0 = __ldg(&b2[0]), b2r1 = __ldg(&b2[1]), b2r2 = __ldg(&b2[2]);
    const __half2* b1h2 = (const __half2*)(smem + SM_B1V);
    const __half2 hz = __floats2half2_rn(0.f, 0.f);

    // ---- lane-invariant ldmatrix addresses ----
    uint32_t rowA = 32u*w + (l & 7) + ((l >> 3) & 1) * 8;   // block 0; block 1 = +16 rows (768B)
    uint32_t colA = (uint32_t)(l >> 4) * 16;
    uint32_t lrow = (l & 7) + ((l >> 4) & 1) * 8;
    uint32_t lcol = ((l >> 3) & 1) * 16;
    uint32_t aB0 = sb + SM_B0 + lrow*48  + lcol;
    uint32_t aB1 = sb + SM_B1 + lrow*272 + lcol;
    uint32_t aB2 = sb + SM_B2 + (uint32_t)(l & 7)*272 + ((l >> 3) & 1)*16;

    int srow = tid;   // each thread stages one full row (32 B)
    uint32_t a0dst0 = sb + SM_A0 + srow*48;

    // ---- prime A0 + H0 buffer 0 (cp.async) ----
    int m = blockIdx.x;
    if (m < NTILES) {
        const char* src = (const char*)&g_f16[(size_t)(m*128+srow)*16];
        CP_ASYNC16(a0dst0,      src);
        CP_ASYNC16(a0dst0 + 16, src + 16);
        int rA = (m*128) / PSTEPS;
        int rB = (m*128 + 127) / PSTEPS;
        int ray = (tid < 64) ? rA : rB;
        int li  = (tid < 64) ? tid : (tid - 64);
        CP_ASYNC4(sb + SM_H0 + (uint32_t)(tid < 64 ? 0 : 256) + li*4,
                  (const char*)&g_h0v[(size_t)ray*128 + li*2]);
        CP_COMMIT();
        CP_WAIT0();
    }
    __syncthreads();

    // ---- preload layer-2 B fragments (tile-invariant) ----
    uint32_t b2f[8][2];
    #pragma unroll
    for (int p = 0; p < 8; p++) LDSM_X2(b2f[p][0], b2f[p][1], aB2 + p*32);

    int buf = 0;

    for (; m < NTILES; m += gridDim.x) {
        int mbase = m * 128;
        int mn = m + gridDim.x;
        bool hn = mn < NTILES;
        if (hn) {   // async-stage next tile into alternate buffer (hidden under compute)
            uint32_t ab = a0dst0 + (uint32_t)(buf^1)*6144u;
            const char* src = (const char*)&g_f16[(size_t)(mn*128+srow)*16];
            CP_ASYNC16(ab,      src);
            CP_ASYNC16(ab + 16, src + 16);
            int rAn = (mn*128) / PSTEPS;
            int rBn = (mn*128 + 127) / PSTEPS;
            int ray = (tid < 64) ? rAn : rBn;
            int li  = (tid < 64) ? tid : (tid - 64);
            CP_ASYNC4(sb + SM_H0 + (uint32_t)(buf^1)*512u + (uint32_t)(tid < 64 ? 0 : 256) + li*4,
                      (const char*)&g_h0v[(size_t)ray*128 + li*2]);
            CP_COMMIT();
        }

        // sample ids: [block][rowhalf]
        int s00 = mbase + 32*w + g;
        int s01 = s00 + 8;
        int s10 = s00 + 16;
        int s11 = s00 + 24;
        int r00 = s00 / PSTEPS, r01 = s01 / PSTEPS;
        int r10 = s10 / PSTEPS, r11 = s11 / PSTEPS;
        int rAc = mbase / PSTEPS;
        const __half* h0sb = (const __half*)(smem + SM_H0 + (uint32_t)buf*512u);
        const __half* hp[2][2] = {
            { h0sb + ((r00 != rAc) ? 128 : 0), h0sb + ((r01 != rAc) ? 128 : 0) },
            { h0sb + ((r10 != rAc) ? 128 : 0), h0sb + ((r11 != rAc) ? 128 : 0) } };

        // ---- layer 0: K=16, f16-acc MMA -> A1 frags in registers ----
        uint32_t aA = sb + SM_A0 + (uint32_t)buf*6144u + rowA*48 + colA;
        uint32_t a0f[2][4];
        LDSM_X4(a0f[0][0],a0f[0][1],a0f[0][2],a0f[0][3], aA);
        LDSM_X4(a0f[1][0],a0f[1][1],a0f[1][2],a0f[1][3], aA + 768);

        uint32_t aF[2][8][4];
        #pragma unroll
        for (int p = 0; p < 8; p++) {
            uint32_t cc[2][2][2];
            #pragma unroll
            for (int b = 0; b < 2; b++)
                #pragma unroll
                for (int hh = 0; hh < 2; hh++) { cc[b][hh][0] = 0u; cc[b][hh][1] = 0u; }
            uint32_t bb0,bb1,bb2,bb3;
            LDSM_X4(bb0,bb1,bb2,bb3, aB0 + p*768);
            #pragma unroll
            for (int b = 0; b < 2; b++) {
                MMA_F16H(cc[b][0], a0f[b][0],a0f[b][1],a0f[b][2],a0f[b][3], bb0,bb1);
                MMA_F16H(cc[b][1], a0f[b][0],a0f[b][1],a0f[b][2],a0f[b][3], bb2,bb3);
            }
            #pragma unroll
            for (int b = 0; b < 2; b++)
                #pragma unroll
                for (int hh = 0; hh < 2; hh++) {
                    int col = p*16 + hh*8 + tg*2;
                    __half2 hA = *(const __half2*)&hp[b][0][col];
                    __half2 hB = *(const __half2*)&hp[b][1][col];
                    __half2 o0 = __hmax2(__hadd2(*(__half2*)&cc[b][hh][0], hA), hz);
                    __half2 o1 = __hmax2(__hadd2(*(__half2*)&cc[b][hh][1], hB), hz);
                    aF[b][p][0+hh*2] = *(uint32_t*)&o0;
                    aF[b][p][1+hh*2] = *(uint32_t*)&o1;
                }
        }

        // ---- layer 1 (K=128, f16-acc) + fused layer 2 MMA (f32-acc) per 16-col chunk ----
        float c2[2][4];
        c2[0][0]=c2[0][1]=c2[0][2]=c2[0][3]=0.f;
        c2[1][0]=c2[1][1]=c2[1][2]=c2[1][3]=0.f;

        #pragma unroll
        for (int p = 0; p < 8; p++) {
            uint32_t cc[2][2][2];
            #pragma unroll
            for (int b = 0; b < 2; b++)
                #pragma unroll
                for (int hh = 0; hh < 2; hh++) { cc[b][hh][0] = 0u; cc[b][hh][1] = 0u; }
            #pragma unroll
            for (int ks = 0; ks < 8; ks++) {
                uint32_t bb0,bb1,bb2,bb3;
                LDSM_X4(bb0,bb1,bb2,bb3, aB1 + p*4352 + ks*32);
                #pragma unroll
                for (int b = 0; b < 2; b++) {
                    MMA_F16H(cc[b][0], aF[b][ks][0],aF[b][ks][1],aF[b][ks][2],aF[b][ks][3], bb0,bb1);
                    MMA_F16H(cc[b][1], aF[b][ks][0],aF[b][ks][1],aF[b][ks][2],aF[b][ks][3], bb2,bb3);
                }
            }
            // bias + relu (half2) -> layer2 A frag; accumulate layer2 MMA (k-chunk = p)
            #pragma unroll
            for (int b = 0; b < 2; b++) {
                uint32_t hf[4];
                #pragma unroll
                for (int hh = 0; hh < 2; hh++) {
                    int col = p*16 + hh*8 + tg*2;
                    __half2 bh = b1h2[col >> 1];
                    __half2 o0 = __hmax2(__hadd2(*(__half2*)&cc[b][hh][0], bh), hz);
                    __half2 o1 = __hmax2(__hadd2(*(__half2*)&cc[b][hh][1], bh), hz);
                    hf[0+hh*2] = *(uint32_t*)&o0;
                    hf[1+hh*2] = *(uint32_t*)&o1;
                }
                MMA_F16(c2[b], hf[0],hf[1],hf[2],hf[3], b2f[p][0], b2f[p][1]);
            }
        }

        // ---- epilogue: sigmoid + weighted atomic, direct from c2 fragments ----
        if (tg == 0) {
            #pragma unroll
            for (int b = 0; b < 2; b++) {
                int sA = (b == 0) ? s00 : s10;
                int sB = (b == 0) ? s01 : s11;
                int rA_ = (b == 0) ? r00 : r10;
                int rB_ = (b == 0) ? r01 : r11;
                float wgA = g_w[sA], wgB = g_w[sB];
                atomicAdd(&out[rA_*3+0], wgA / (1.0f + __expf(-(c2[b][0] + b2r0))));
                atomicAdd(&out[rA_*3+1], wgA / (1.0f + __expf(-(c2[b][1] + b2r1))));
                atomicAdd(&out[rB_*3+0], wgB / (1.0f + __expf(-(c2[b][2] + b2r0))));
                atomicAdd(&out[rB_*3+1], wgB / (1.0f + __expf(-(c2[b][3] + b2r1))));
            }
        } else if (tg == 1) {
            #pragma unroll
            for (int b = 0; b < 2; b++) {
                int sA = (b == 0) ? s00 : s10;
                int sB = (b == 0) ? s01 : s11;
                int rA_ = (b == 0) ? r00 : r10;
                int rB_ = (b == 0) ? r01 : r11;
                float wgA = g_w[sA], wgB = g_w[sB];
                atomicAdd(&out[rA_*3+2], wgA / (1.0f + __expf(-(c2[b][0] + b2r2))));
                atomicAdd(&out[rB_*3+2], wgB / (1.0f + __expf(-(c2[b][2] + b2r2))));
            }
        }

        if (hn) CP_WAIT0();
        __syncthreads();
        buf ^= 1;
    }
}

// ---------------- launcher ----------------
extern "C" void kernel_launch(void* const* d_in, const int* in_sizes, int n_in,
                              void* d_out, int out_size)
{
    const float* rays_o   = (const float*)d_in[0];
    const float* rays_d   = (const float*)d_in[1];
    const float* viewdirs = (const float*)d_in[2];
    const float* dgrid    = (const float*)d_in[3];
    const float* k0g      = (const float*)d_in[4];
    const float* w0 = (const float*)d_in[5];
    const float* b0 = (const float*)d_in[6];
    const float* w1 = (const float*)d_in[7];
    const float* b1 = (const float*)d_in[8];
    const float* w2 = (const float*)d_in[9];
    const float* b2 = (const float*)d_in[10];
    const int* stepsize = (const int*)d_in[11];
    float* out = (float*)d_out;

    cudaFuncSetAttribute(k_mlp, cudaFuncAttributeMaxDynamicSharedMemorySize, SMEM_TOTAL);

    k_pack<<<(S3 + 255) / 256, 256>>>(dgrid, k0g);
    k_sample<<<(N_RAYS * 32 + 255) / 256, 256>>>(rays_o, rays_d, viewdirs, stepsize, out);
    k_h0v<<<(N_RAYS * 128) / 256, 256>>>(w0, b0);
    k_mlp<<<GRID_MLP, 128, SMEM_TOTAL>>>(w0, b0, w1, b1, w2, b2, out);
}